// round 12
// baseline (speedup 1.0000x reference)
#include <cuda_runtime.h>
#include <cuda_bf16.h>
#include <math.h>

#define NB 8192
#define NC 32000
#define NCTA 1184   // 148 SMs x 8 CTAs/SM -> exactly one wave

// device-global accumulator (allocation-free). Starts 0; finalize resets it
// after every call so graph replays are correct.
__device__ double g_sum = 0.0;

__inline__ __device__ float warpReduceSum(float v) {
#pragma unroll
    for (int o = 16; o > 0; o >>= 1)
        v += __shfl_down_sync(0xffffffffu, v, o);
    return v;
}

__global__ __launch_bounds__(256) void row_loss_kernel(
    const float* __restrict__ y_pred,
    const int* __restrict__ y_true)   // JAX x64-disabled: int64 degrades to int32
{
    __shared__ float sh[8];
    const int lane = threadIdx.x & 31;
    const int wid  = threadIdx.x >> 5;

    // persistent grid-stride over rows: one wave, no wave-transition overhead
    for (int row = blockIdx.x; row < NB; row += NCTA) {
        const float* rowp = y_pred + (size_t)row * NC;
        const float4* p4 = reinterpret_cast<const float4*>(rowp);
        const int n4 = NC / 4;  // 8000

        float s = 0.0f;
#pragma unroll 4
        for (int i = threadIdx.x; i < n4; i += 256) {
            float4 v = __ldcs(p4 + i);   // read-once: evict-first
            s += __expf(v.x) + __expf(v.y) + __expf(v.z) + __expf(v.w);
        }

        // block reduce (fp32)
        s = warpReduceSum(s);
        if (lane == 0) sh[wid] = s;
        __syncthreads();
        if (threadIdx.x == 0) {
            float v = 0.0f;
#pragma unroll
            for (int w = 0; w < 8; w++) v += sh[w];
            int t = y_true[row];
            t = (t < 0) ? 0 : ((t >= NC) ? NC - 1 : t);   // crash guard
            const float pt = __ldg(rowp + t);
            const float et = __expf(pt);
            const float sneg = v - et;                    // sum over negatives
            const float loss = log1pf(sneg * __expf(-pt));
            // fire-and-forget: REDG.ADD.F64, no return -> no retirement wait
            atomicAdd(&g_sum, (double)loss);
        }
        __syncthreads();   // protect sh[] reuse across row iterations
    }
}

__global__ void finalize_kernel(float* __restrict__ out)
{
    // PDL: resident early; wait for primary grid full completion (all REDs
    // from the whole grid are visible after this).
    cudaGridDependencySynchronize();
    if (threadIdx.x == 0) {
        out[0] = (float)(g_sum / (double)NB);
        g_sum = 0.0;                                  // reset for next replay
    }
}

extern "C" void kernel_launch(void* const* d_in, const int* in_sizes, int n_in,
                              void* d_out, int out_size)
{
    const float* y_pred = (const float*)d_in[0];
    const int*   y_true = (const int*)d_in[1];
    float* out = (float*)d_out;

    row_loss_kernel<<<NCTA, 256>>>(y_pred, y_true);

    // PDL finalize: launch overlaps the row kernel's tail.
    cudaLaunchAttribute attrs[1];
    attrs[0].id = cudaLaunchAttributeProgrammaticStreamSerialization;
    attrs[0].val.programmaticStreamSerializationAllowed = 1;

    cudaLaunchConfig_t cfg = {};
    cfg.gridDim  = dim3(1, 1, 1);
    cfg.blockDim = dim3(32, 1, 1);
    cfg.dynamicSmemBytes = 0;
    cfg.stream = 0;
    cfg.attrs = attrs;
    cfg.numAttrs = 1;

    cudaLaunchKernelEx(&cfg, finalize_kernel, out);
}

// round 13
// speedup vs baseline: 1.0236x; 1.0236x over previous
#include <cuda_runtime.h>
#include <cuda_bf16.h>
#include <math.h>

#define NB 8192
#define NC 32000
#define TPB 512

// device-global accumulator (allocation-free). Starts 0; finalize resets it
// after every call so graph replays are correct.
__device__ double g_sum = 0.0;

__inline__ __device__ float warpReduceSum(float v) {
#pragma unroll
    for (int o = 16; o > 0; o >>= 1)
        v += __shfl_down_sync(0xffffffffu, v, o);
    return v;
}

__global__ __launch_bounds__(TPB) void row_loss_kernel(
    const float* __restrict__ y_pred,
    const int* __restrict__ y_true)   // JAX x64-disabled: int64 degrades to int32
{
    const int row = blockIdx.x;
    const float* rowp = y_pred + (size_t)row * NC;
    const float4* p4 = reinterpret_cast<const float4*>(rowp);
    const int n4 = NC / 4;  // 8000

    float s = 0.0f;
#pragma unroll 4
    for (int i = threadIdx.x; i < n4; i += TPB) {
        float4 v = __ldcs(p4 + i);   // read-once: evict-first, keep L2 clean
        s += __expf(v.x) + __expf(v.y) + __expf(v.z) + __expf(v.w);
    }

    // block reduce (fp32)
    __shared__ float sh[TPB / 32];
    const int lane = threadIdx.x & 31;
    const int wid  = threadIdx.x >> 5;
    s = warpReduceSum(s);
    if (lane == 0) sh[wid] = s;
    __syncthreads();
    if (threadIdx.x == 0) {
        float v = 0.0f;
#pragma unroll
        for (int w = 0; w < TPB / 32; w++) v += sh[w];
        int t = y_true[row];
        t = (t < 0) ? 0 : ((t >= NC) ? NC - 1 : t);   // crash guard
        const float pt = __ldg(rowp + t);
        const float et = __expf(pt);
        const float sneg = v - et;                    // sum over negatives
        const float loss = log1pf(sneg * __expf(-pt));
        // fire-and-forget: REDG.ADD.F64, no return -> no retirement wait
        atomicAdd(&g_sum, (double)loss);
    }
}

__global__ void finalize_kernel(float* __restrict__ out)
{
    // PDL: resident early; wait for primary grid full completion (all REDs
    // from the whole grid are visible after this).
    cudaGridDependencySynchronize();
    if (threadIdx.x == 0) {
        out[0] = (float)(g_sum / (double)NB);
        g_sum = 0.0;                                  // reset for next replay
    }
}

extern "C" void kernel_launch(void* const* d_in, const int* in_sizes, int n_in,
                              void* d_out, int out_size)
{
    const float* y_pred = (const float*)d_in[0];
    const int*   y_true = (const int*)d_in[1];
    float* out = (float*)d_out;

    row_loss_kernel<<<NB, TPB>>>(y_pred, y_true);

    // PDL finalize: launch overlaps the row kernel's tail.
    cudaLaunchAttribute attrs[1];
    attrs[0].id = cudaLaunchAttributeProgrammaticStreamSerialization;
    attrs[0].val.programmaticStreamSerializationAllowed = 1;

    cudaLaunchConfig_t cfg = {};
    cfg.gridDim  = dim3(1, 1, 1);
    cfg.blockDim = dim3(32, 1, 1);
    cfg.dynamicSmemBytes = 0;
    cfg.stream = 0;
    cfg.attrs = attrs;
    cfg.numAttrs = 1;

    cudaLaunchKernelEx(&cfg, finalize_kernel, out);
}